// round 13
// baseline (speedup 1.0000x reference)
#include <cuda_runtime.h>
#include <cuda_bf16.h>
#include <cstdint>

#define CH   64
#define HH   112
#define WW   112
#define HWS  12544
#define BB   4
#define KK   49
#define NPIX (BB*HWS)

// Scratch (device globals — no allocation allowed). Zero-initialized at load.
__device__ __align__(16) float g_y0  [BB*CH*HWS];   // reduce output (pre-BN1)
__device__ __align__(16) float g_kern[BB*KK*HWS];   // per-pixel kernels
__device__ __align__(16) float g_out0[BB*CH*HWS];   // involution output (pre-BN2)
__device__ float g_stats1[2*CH];
__device__ float g_stats2[2*CH];

// ---- packed bf16 helpers ----
__device__ __forceinline__ uint32_t pack_bf2(float lo, float hi) {
    __nv_bfloat162 p = __floats2bfloat162_rn(lo, hi);
    uint32_t u; *(__nv_bfloat162*)&u = p; return u;
}
__device__ __forceinline__ float bf2_lo(uint32_t u) { return __uint_as_float(u << 16); }
__device__ __forceinline__ float bf2_hi(uint32_t u) { return __uint_as_float(u & 0xFFFF0000u); }

__device__ __forceinline__ void mma_bf16(float c[4], uint32_t a0, uint32_t a1,
                                         uint32_t a2, uint32_t a3,
                                         uint32_t b0, uint32_t b1) {
    asm volatile(
        "mma.sync.aligned.m16n8k16.row.col.f32.bf16.bf16.f32 "
        "{%0,%1,%2,%3}, {%4,%5,%6,%7}, {%8,%9}, {%0,%1,%2,%3};"
        : "+f"(c[0]), "+f"(c[1]), "+f"(c[2]), "+f"(c[3])
        : "r"(a0), "r"(a1), "r"(a2), "r"(a3), "r"(b0), "r"(b1));
}

// ================================================================ K1: reduce GEMM (HMMA bf16x3) + stats1
#define APAD 37
#define BPAD 33
#define OFF_AHI 0
#define OFF_ALO (128*APAD)
#define OFF_BHI (2*128*APAD)
#define OFF_BLO (OFF_BHI + 64*BPAD)
#define RED_WORDS (OFF_BLO + 64*BPAD)
#define RED_SMEM (RED_WORDS*4)

__global__ __launch_bounds__(256) void k_reduce(const float* __restrict__ x,
                                                const float* __restrict__ wred) {
    extern __shared__ __align__(16) uint32_t smw[];
    uint32_t* ahix = smw + OFF_AHI;
    uint32_t* alox = smw + OFF_ALO;
    uint32_t* whix = smw + OFF_BHI;
    uint32_t* wlox = smw + OFF_BLO;

    const int t = threadIdx.x;
    const int wid = t >> 5, lid = t & 31;
    const int b = blockIdx.y;
    const int pix0 = blockIdx.x * 128;

    if (blockIdx.x == 0 && b == 0 && t < 2*CH) g_stats2[t] = 0.f;

    const float* xb = x + (size_t)b*CH*HWS + pix0;
    #pragma unroll
    for (int l = t; l < 32*32; l += 256) {
        int c2 = l >> 5, p4 = l & 31;
        float4 va = *(const float4*)(xb + (size_t)(2*c2)*HWS + p4*4);
        float4 vb = *(const float4*)(xb + (size_t)(2*c2+1)*HWS + p4*4);
        float a0[4] = {va.x, va.y, va.z, va.w};
        float b0[4] = {vb.x, vb.y, vb.z, vb.w};
        #pragma unroll
        for (int j = 0; j < 4; j++) {
            uint32_t hp = pack_bf2(a0[j], b0[j]);
            uint32_t lp = pack_bf2(a0[j] - bf2_lo(hp), b0[j] - bf2_hi(hp));
            ahix[(p4*4 + j)*APAD + c2] = hp;
            alox[(p4*4 + j)*APAD + c2] = lp;
        }
    }
    #pragma unroll
    for (int l = t; l < 32*64; l += 256) {
        int c2 = l & 31, n = l >> 5;
        float v0 = wred[n*CH + 2*c2];
        float v1 = wred[n*CH + 2*c2 + 1];
        uint32_t hp = pack_bf2(v0, v1);
        uint32_t lp = pack_bf2(v0 - bf2_lo(hp), v1 - bf2_hi(hp));
        whix[n*BPAD + c2] = hp;
        wlox[n*BPAD + c2] = lp;
    }
    __syncthreads();

    const int gid = lid >> 2, tig = lid & 3;
    const int p0 = wid*16 + gid;
    float acc[8][4];
    #pragma unroll
    for (int i = 0; i < 8; i++)
        #pragma unroll
        for (int j = 0; j < 4; j++) acc[i][j] = 0.f;

    #pragma unroll
    for (int ks = 0; ks < 4; ks++) {
        const int j0 = tig + ks*8, j1 = tig + 4 + ks*8;
        uint32_t ah0 = ahix[p0*APAD + j0],     ah1 = ahix[(p0+8)*APAD + j0];
        uint32_t ah2 = ahix[p0*APAD + j1],     ah3 = ahix[(p0+8)*APAD + j1];
        uint32_t al0 = alox[p0*APAD + j0],     al1 = alox[(p0+8)*APAD + j0];
        uint32_t al2 = alox[p0*APAD + j1],     al3 = alox[(p0+8)*APAD + j1];
        #pragma unroll
        for (int nt = 0; nt < 8; nt++) {
            const int n = nt*8 + gid;
            uint32_t bh0 = whix[n*BPAD + j0], bh1 = whix[n*BPAD + j1];
            uint32_t bl0 = wlox[n*BPAD + j0], bl1 = wlox[n*BPAD + j1];
            mma_bf16(acc[nt], ah0, ah1, ah2, ah3, bh0, bh1);
            mma_bf16(acc[nt], ah0, ah1, ah2, ah3, bl0, bl1);
            mma_bf16(acc[nt], al0, al1, al2, al3, bh0, bh1);
        }
    }
    __syncthreads();

    float* pad = (float*)smw;           // [64 o][129]
    #pragma unroll
    for (int nt = 0; nt < 8; nt++) {
        const int o = nt*8 + 2*tig;
        pad[o*129 + p0]           = acc[nt][0];
        pad[(o+1)*129 + p0]       = acc[nt][1];
        pad[o*129 + p0 + 8]       = acc[nt][2];
        pad[(o+1)*129 + p0 + 8]   = acc[nt][3];
    }
    __syncthreads();

    float* y0b = g_y0 + (size_t)b*CH*HWS + pix0;
    #pragma unroll
    for (int l = t; l < CH*128; l += 256) {
        int o = l >> 7, p = l & 127;
        y0b[(size_t)o*HWS + p] = pad[o*129 + p];
    }
    {
        const int o = t & 63, quarter = t >> 6;
        float s = 0.f, q = 0.f;
        #pragma unroll 8
        for (int i = 0; i < 32; i++) {
            float v = pad[o*129 + quarter*32 + i];
            s += v; q = fmaf(v, v, q);
        }
        atomicAdd(&g_stats1[o], s);
        atomicAdd(&g_stats1[CH + o], q);
    }
}

// ================================================================ K2: bn1 + span GEMM (HMMA bf16x3) -> g_kern
#define SPAD 33
#define S_YHI 0
#define S_YLO (128*SPAD)
#define S_WHI (2*128*SPAD)
#define S_WLO (S_WHI + 56*SPAD)
#define S_BN  (S_WLO + 56*SPAD)
#define SPAN_WORDS (S_BN + 128)
#define SPAN_SMEM (SPAN_WORDS*4)

__global__ __launch_bounds__(256) void k_span(const float* __restrict__ wspan,
                                              const float* __restrict__ g1,
                                              const float* __restrict__ b1) {
    extern __shared__ __align__(16) uint32_t smw[];
    uint32_t* yhi = smw + S_YHI;
    uint32_t* ylo = smw + S_YLO;
    uint32_t* whi = smw + S_WHI;
    uint32_t* wlo = smw + S_WLO;
    float* bn = (float*)(smw + S_BN);

    const int t = threadIdx.x;
    const int wid = t >> 5, lid = t & 31;
    const int b = blockIdx.y;
    const int pix0 = blockIdx.x * 128;

    if (t < CH) {
        const float n = (float)NPIX;
        float mean = g_stats1[t] / n;
        float var  = g_stats1[CH + t] / n - mean*mean;
        float sc = g1[t] * rsqrtf(var + 1e-5f);
        bn[t]      = sc;
        bn[CH + t] = b1[t] - mean*sc;
    }
    #pragma unroll
    for (int l = t; l < 56*32; l += 256) {
        int n = l >> 5, c2 = l & 31;
        float v0 = 0.f, v1 = 0.f;
        if (n < KK) { v0 = wspan[n*CH + 2*c2]; v1 = wspan[n*CH + 2*c2 + 1]; }
        uint32_t hp = pack_bf2(v0, v1);
        uint32_t lp = pack_bf2(v0 - bf2_lo(hp), v1 - bf2_hi(hp));
        whi[n*SPAD + c2] = hp;
        wlo[n*SPAD + c2] = lp;
    }
    __syncthreads();

    const float* y0b = g_y0 + (size_t)b*CH*HWS + pix0;
    #pragma unroll
    for (int l = t; l < 32*32; l += 256) {
        int c2 = l >> 5, p4 = l & 31;
        float4 va = *(const float4*)(y0b + (size_t)(2*c2)*HWS + p4*4);
        float4 vb = *(const float4*)(y0b + (size_t)(2*c2+1)*HWS + p4*4);
        float a0[4] = {va.x, va.y, va.z, va.w};
        float b0v[4] = {vb.x, vb.y, vb.z, vb.w};
        const float s0 = bn[2*c2], h0 = bn[CH + 2*c2];
        const float s1 = bn[2*c2+1], h1 = bn[CH + 2*c2+1];
        #pragma unroll
        for (int j = 0; j < 4; j++) {
            float v0 = fmaxf(fmaf(a0[j], s0, h0), 0.f);
            float v1 = fmaxf(fmaf(b0v[j], s1, h1), 0.f);
            uint32_t hp = pack_bf2(v0, v1);
            uint32_t lp = pack_bf2(v0 - bf2_lo(hp), v1 - bf2_hi(hp));
            yhi[(p4*4 + j)*SPAD + c2] = hp;
            ylo[(p4*4 + j)*SPAD + c2] = lp;
        }
    }
    __syncthreads();

    const int gid = lid >> 2, tig = lid & 3;
    const int p0 = wid*16 + gid;
    float sacc[7][4];
    #pragma unroll
    for (int i = 0; i < 7; i++)
        #pragma unroll
        for (int j = 0; j < 4; j++) sacc[i][j] = 0.f;

    #pragma unroll
    for (int ks4 = 0; ks4 < 4; ks4++) {
        const int j0 = tig + ks4*8, j1 = j0 + 4;
        uint32_t ah0 = yhi[p0*SPAD + j0],     ah1 = yhi[(p0+8)*SPAD + j0];
        uint32_t ah2 = yhi[p0*SPAD + j1],     ah3 = yhi[(p0+8)*SPAD + j1];
        uint32_t al0 = ylo[p0*SPAD + j0],     al1 = ylo[(p0+8)*SPAD + j0];
        uint32_t al2 = ylo[p0*SPAD + j1],     al3 = ylo[(p0+8)*SPAD + j1];
        #pragma unroll
        for (int nt = 0; nt < 7; nt++) {
            const int n = nt*8 + gid;
            uint32_t bh0 = whi[n*SPAD + j0], bh1 = whi[n*SPAD + j1];
            uint32_t bl0 = wlo[n*SPAD + j0], bl1 = wlo[n*SPAD + j1];
            mma_bf16(sacc[nt], ah0, ah1, ah2, ah3, bh0, bh1);
            mma_bf16(sacc[nt], ah0, ah1, ah2, ah3, bl0, bl1);
            mma_bf16(sacc[nt], al0, al1, al2, al3, bh0, bh1);
        }
    }
    __syncthreads();

    float* pad = (float*)smw;           // [56 o][129]
    #pragma unroll
    for (int nt = 0; nt < 7; nt++) {
        const int o = nt*8 + 2*tig;
        pad[o*129 + p0]           = sacc[nt][0];
        pad[(o+1)*129 + p0]       = sacc[nt][1];
        pad[o*129 + p0 + 8]       = sacc[nt][2];
        pad[(o+1)*129 + p0 + 8]   = sacc[nt][3];
    }
    __syncthreads();

    float* kb = g_kern + (size_t)b*KK*HWS + pix0;
    #pragma unroll
    for (int l = t; l < KK*128; l += 256) {
        int o = l >> 7, p = l & 127;
        kb[(size_t)o*HWS + p] = pad[o*129 + p];
    }
}

// ================================================================ K3: involution + stats2
// Grid (98, B, 4): 128-pixel tile x 16-channel quarter. Thread: 2 channels x 4 pixels.
// kv loaded inside kw-loop (4 transient regs) -> live set ~48 regs -> 5 blocks/SM.
__global__ __launch_bounds__(256, 5) void k_invol(const float* __restrict__ x) {
    __shared__ __align__(16) float ks[KK*128];
    const int t = threadIdx.x;
    const int wg = t & 31;          // pixel quad
    const int cl = t >> 5;          // channel pair group (0..7)
    const int b = blockIdx.y;
    const int z = blockIdx.z;       // 0..3
    const int pix0 = blockIdx.x * 128;
    const int ch0 = z*16 + cl*2;

    const float* kb = g_kern + (size_t)b*KK*HWS + pix0;
    #pragma unroll
    for (int l = t; l < KK*32; l += 256) {
        int p = l >> 5, q = l & 31;
        ((float4*)(ks + p*128))[q] = *(const float4*)(kb + (size_t)p*HWS + q*4);
    }
    __syncthreads();

    const int pp = pix0 + wg*4;
    const int h  = pp / WW;
    const int w0 = pp - h*WW;

    float acc[2][4];
    #pragma unroll
    for (int cc = 0; cc < 2; cc++)
        #pragma unroll
        for (int j = 0; j < 4; j++) acc[cc][j] = 0.f;

    const float* xbase = x + ((size_t)b*CH + ch0)*HWS;
    const float4 zero4 = make_float4(0.f, 0.f, 0.f, 0.f);
    #pragma unroll
    for (int kh = 0; kh < 7; kh++) {
        const int row = h + kh - 3;
        if (row < 0 || row >= HH) continue;
        const float* xrow = xbase + (size_t)row*WW;
        float xr[2][10];
        #pragma unroll
        for (int cc = 0; cc < 2; cc++) {
            const float* xc = xrow + (size_t)cc*HWS;
            float4 v1 = *(const float4*)(xc + w0);
            float4 v0 = (w0 >= 4)   ? *(const float4*)(xc + w0 - 4) : zero4;
            float4 v2 = (w0 <= 104) ? *(const float4*)(xc + w0 + 4) : zero4;
            xr[cc][0] = v0.y; xr[cc][1] = v0.z; xr[cc][2] = v0.w;
            xr[cc][3] = v1.x; xr[cc][4] = v1.y; xr[cc][5] = v1.z; xr[cc][6] = v1.w;
            xr[cc][7] = v2.x; xr[cc][8] = v2.y; xr[cc][9] = v2.z;
        }
        #pragma unroll
        for (int kw = 0; kw < 7; kw++) {
            float4 kv = ((const float4*)(ks + (kh*7 + kw)*128))[wg];
            #pragma unroll
            for (int cc = 0; cc < 2; cc++) {
                acc[cc][0] = fmaf(xr[cc][0 + kw], kv.x, acc[cc][0]);
                acc[cc][1] = fmaf(xr[cc][1 + kw], kv.y, acc[cc][1]);
                acc[cc][2] = fmaf(xr[cc][2 + kw], kv.z, acc[cc][2]);
                acc[cc][3] = fmaf(xr[cc][3 + kw], kv.w, acc[cc][3]);
            }
        }
    }

    float* ob = g_out0 + ((size_t)b*CH + ch0)*HWS + pp;
    #pragma unroll
    for (int cc = 0; cc < 2; cc++) {
        float4 v; v.x = acc[cc][0]; v.y = acc[cc][1]; v.z = acc[cc][2]; v.w = acc[cc][3];
        *((float4*)(ob + (size_t)cc*HWS)) = v;
        float s = v.x + v.y + v.z + v.w;
        float q = v.x*v.x + v.y*v.y + v.z*v.z + v.w*v.w;
        #pragma unroll
        for (int off = 16; off; off >>= 1) {
            s += __shfl_down_sync(0xffffffffu, s, off);
            q += __shfl_down_sync(0xffffffffu, q, off);
        }
        if (wg == 0) {
            atomicAdd(&g_stats2[ch0 + cc], s);
            atomicAdd(&g_stats2[CH + ch0 + cc], q);
        }
    }
}

// ================================================================ K4: bn2 finalize + affine + PReLU
// Grid (BB*CH, 4): each block handles a quarter of one (b,c) channel image.
__global__ __launch_bounds__(256) void k_apply(const float* __restrict__ gamma,
                                               const float* __restrict__ beta,
                                               const float* __restrict__ alpha,
                                               float* __restrict__ out) {
    __shared__ float s_p[3];
    const int t = threadIdx.x;
    const int bc = blockIdx.x;
    const int chunk = blockIdx.y;        // 0..3, 784 float4 each
    const int c = bc & (CH-1);

    if (t == 0) {
        const float n = (float)NPIX;
        float mean = g_stats2[c] / n;
        float var  = g_stats2[CH + c] / n - mean*mean;
        float sc = gamma[c] * rsqrtf(var + 1e-3f);
        s_p[0] = sc;
        s_p[1] = beta[c] - mean*sc;
        s_p[2] = alpha[c];
    }
    if (bc == 0 && chunk == 0 && t < 2*CH) g_stats1[t] = 0.f;
    __syncthreads();

    const float sc = s_p[0], sh = s_p[1], al = s_p[2];
    const int base = chunk * (HWS/16);   // 784 float4 per chunk
    const float4* src = (const float4*)(g_out0 + (size_t)bc*HWS) + base;
    float4* dst = (float4*)(out + (size_t)bc*HWS) + base;
    #pragma unroll
    for (int i = t; i < HWS/16; i += 256) {
        float4 v = src[i];
        float u;
        u = fmaf(v.x, sc, sh); v.x = u > 0.f ? u : al*u;
        u = fmaf(v.y, sc, sh); v.y = u > 0.f ? u : al*u;
        u = fmaf(v.z, sc, sh); v.z = u > 0.f ? u : al*u;
        u = fmaf(v.w, sc, sh); v.w = u > 0.f ? u : al*u;
        dst[i] = v;
    }
}

// ----------------------------------------------------------------
extern "C" void kernel_launch(void* const* d_in, const int* in_sizes, int n_in,
                              void* d_out, int out_size) {
    const float* x     = (const float*)d_in[0];
    const float* wred  = (const float*)d_in[1];
    const float* g1    = (const float*)d_in[2];
    const float* b1    = (const float*)d_in[3];
    const float* wspan = (const float*)d_in[4];
    const float* g2    = (const float*)d_in[5];
    const float* b2    = (const float*)d_in[6];
    const float* alpha = (const float*)d_in[7];
    float* out = (float*)d_out;

    cudaFuncSetAttribute(k_reduce, cudaFuncAttributeMaxDynamicSharedMemorySize, RED_SMEM);
    cudaFuncSetAttribute(k_span,   cudaFuncAttributeMaxDynamicSharedMemorySize, SPAN_SMEM);

    k_reduce<<<dim3(HWS/128, BB), 256, RED_SMEM>>>(x, wred);
    k_span  <<<dim3(HWS/128, BB), 256, SPAN_SMEM>>>(wspan, g1, b1);
    k_invol <<<dim3(HWS/128, BB, 4), 256>>>(x);
    k_apply <<<dim3(BB*CH, 4), 256>>>(g2, b2, alpha, out);
}

// round 14
// speedup vs baseline: 1.0430x; 1.0430x over previous
#include <cuda_runtime.h>
#include <cuda_bf16.h>
#include <cstdint>

#define CH   64
#define HH   112
#define WW   112
#define HWS  12544
#define BB   4
#define KK   49
#define NPIX (BB*HWS)

// Scratch (device globals — no allocation allowed). Zero-initialized at load.
__device__ __align__(16) float g_y0  [BB*CH*HWS];   // reduce output (pre-BN1)
__device__ __align__(16) float g_kern[BB*KK*HWS];   // per-pixel kernels
__device__ __align__(16) float g_out0[BB*CH*HWS];   // involution output (pre-BN2)
__device__ float g_stats1[2*CH];
__device__ float g_stats2[2*CH];

// ---- packed bf16 helpers ----
__device__ __forceinline__ uint32_t pack_bf2(float lo, float hi) {
    __nv_bfloat162 p = __floats2bfloat162_rn(lo, hi);
    uint32_t u; *(__nv_bfloat162*)&u = p; return u;
}
__device__ __forceinline__ float bf2_lo(uint32_t u) { return __uint_as_float(u << 16); }
__device__ __forceinline__ float bf2_hi(uint32_t u) { return __uint_as_float(u & 0xFFFF0000u); }

__device__ __forceinline__ void mma_bf16(float c[4], uint32_t a0, uint32_t a1,
                                         uint32_t a2, uint32_t a3,
                                         uint32_t b0, uint32_t b1) {
    asm volatile(
        "mma.sync.aligned.m16n8k16.row.col.f32.bf16.bf16.f32 "
        "{%0,%1,%2,%3}, {%4,%5,%6,%7}, {%8,%9}, {%0,%1,%2,%3};"
        : "+f"(c[0]), "+f"(c[1]), "+f"(c[2]), "+f"(c[3])
        : "r"(a0), "r"(a1), "r"(a2), "r"(a3), "r"(b0), "r"(b1));
}

// ================================================================ K1: reduce GEMM (HMMA bf16x3) + stats1
#define APAD 37
#define BPAD 33
#define OFF_AHI 0
#define OFF_ALO (128*APAD)
#define OFF_BHI (2*128*APAD)
#define OFF_BLO (OFF_BHI + 64*BPAD)
#define RED_WORDS (OFF_BLO + 64*BPAD)
#define RED_SMEM (RED_WORDS*4)

__global__ __launch_bounds__(256, 4) void k_reduce(const float* __restrict__ x,
                                                   const float* __restrict__ wred) {
    extern __shared__ __align__(16) uint32_t smw[];
    uint32_t* ahix = smw + OFF_AHI;
    uint32_t* alox = smw + OFF_ALO;
    uint32_t* whix = smw + OFF_BHI;
    uint32_t* wlox = smw + OFF_BLO;

    const int t = threadIdx.x;
    const int wid = t >> 5, lid = t & 31;
    const int b = blockIdx.y;
    const int pix0 = blockIdx.x * 128;

    if (blockIdx.x == 0 && b == 0 && t < 2*CH) g_stats2[t] = 0.f;

    const float* xb = x + (size_t)b*CH*HWS + pix0;
    #pragma unroll
    for (int l = t; l < 32*32; l += 256) {
        int c2 = l >> 5, p4 = l & 31;
        float4 va = *(const float4*)(xb + (size_t)(2*c2)*HWS + p4*4);
        float4 vb = *(const float4*)(xb + (size_t)(2*c2+1)*HWS + p4*4);
        float a0[4] = {va.x, va.y, va.z, va.w};
        float b0[4] = {vb.x, vb.y, vb.z, vb.w};
        #pragma unroll
        for (int j = 0; j < 4; j++) {
            uint32_t hp = pack_bf2(a0[j], b0[j]);
            uint32_t lp = pack_bf2(a0[j] - bf2_lo(hp), b0[j] - bf2_hi(hp));
            ahix[(p4*4 + j)*APAD + c2] = hp;
            alox[(p4*4 + j)*APAD + c2] = lp;
        }
    }
    #pragma unroll
    for (int l = t; l < 32*64; l += 256) {
        int c2 = l & 31, n = l >> 5;
        float v0 = wred[n*CH + 2*c2];
        float v1 = wred[n*CH + 2*c2 + 1];
        uint32_t hp = pack_bf2(v0, v1);
        uint32_t lp = pack_bf2(v0 - bf2_lo(hp), v1 - bf2_hi(hp));
        whix[n*BPAD + c2] = hp;
        wlox[n*BPAD + c2] = lp;
    }
    __syncthreads();

    const int gid = lid >> 2, tig = lid & 3;
    const int p0 = wid*16 + gid;
    float acc[8][4];
    #pragma unroll
    for (int i = 0; i < 8; i++)
        #pragma unroll
        for (int j = 0; j < 4; j++) acc[i][j] = 0.f;

    #pragma unroll
    for (int ks = 0; ks < 4; ks++) {
        const int j0 = tig + ks*8, j1 = tig + 4 + ks*8;
        uint32_t ah0 = ahix[p0*APAD + j0],     ah1 = ahix[(p0+8)*APAD + j0];
        uint32_t ah2 = ahix[p0*APAD + j1],     ah3 = ahix[(p0+8)*APAD + j1];
        uint32_t al0 = alox[p0*APAD + j0],     al1 = alox[(p0+8)*APAD + j0];
        uint32_t al2 = alox[p0*APAD + j1],     al3 = alox[(p0+8)*APAD + j1];
        #pragma unroll
        for (int nt = 0; nt < 8; nt++) {
            const int n = nt*8 + gid;
            uint32_t bh0 = whix[n*BPAD + j0], bh1 = whix[n*BPAD + j1];
            uint32_t bl0 = wlox[n*BPAD + j0], bl1 = wlox[n*BPAD + j1];
            mma_bf16(acc[nt], ah0, ah1, ah2, ah3, bh0, bh1);
            mma_bf16(acc[nt], ah0, ah1, ah2, ah3, bl0, bl1);
            mma_bf16(acc[nt], al0, al1, al2, al3, bh0, bh1);
        }
    }
    __syncthreads();

    float* pad = (float*)smw;           // [64 o][129]
    #pragma unroll
    for (int nt = 0; nt < 8; nt++) {
        const int o = nt*8 + 2*tig;
        pad[o*129 + p0]           = acc[nt][0];
        pad[(o+1)*129 + p0]       = acc[nt][1];
        pad[o*129 + p0 + 8]       = acc[nt][2];
        pad[(o+1)*129 + p0 + 8]   = acc[nt][3];
    }
    __syncthreads();

    float* y0b = g_y0 + (size_t)b*CH*HWS + pix0;
    #pragma unroll
    for (int l = t; l < CH*128; l += 256) {
        int o = l >> 7, p = l & 127;
        y0b[(size_t)o*HWS + p] = pad[o*129 + p];
    }
    {
        const int o = t & 63, quarter = t >> 6;
        float s = 0.f, q = 0.f;
        #pragma unroll 8
        for (int i = 0; i < 32; i++) {
            float v = pad[o*129 + quarter*32 + i];
            s += v; q = fmaf(v, v, q);
        }
        atomicAdd(&g_stats1[o], s);
        atomicAdd(&g_stats1[CH + o], q);
    }
}

// ================================================================ K2: bn1 + span GEMM (HMMA bf16x3) -> g_kern
#define SPAD 33
#define S_YHI 0
#define S_YLO (128*SPAD)
#define S_WHI (2*128*SPAD)
#define S_WLO (S_WHI + 56*SPAD)
#define S_BN  (S_WLO + 56*SPAD)
#define SPAN_WORDS (S_BN + 128)
#define SPAN_SMEM (SPAN_WORDS*4)

__global__ __launch_bounds__(256, 4) void k_span(const float* __restrict__ wspan,
                                                 const float* __restrict__ g1,
                                                 const float* __restrict__ b1) {
    extern __shared__ __align__(16) uint32_t smw[];
    uint32_t* yhi = smw + S_YHI;
    uint32_t* ylo = smw + S_YLO;
    uint32_t* whi = smw + S_WHI;
    uint32_t* wlo = smw + S_WLO;
    float* bn = (float*)(smw + S_BN);

    const int t = threadIdx.x;
    const int wid = t >> 5, lid = t & 31;
    const int b = blockIdx.y;
    const int pix0 = blockIdx.x * 128;

    if (t < CH) {
        const float n = (float)NPIX;
        float mean = g_stats1[t] / n;
        float var  = g_stats1[CH + t] / n - mean*mean;
        float sc = g1[t] * rsqrtf(var + 1e-5f);
        bn[t]      = sc;
        bn[CH + t] = b1[t] - mean*sc;
    }
    #pragma unroll
    for (int l = t; l < 56*32; l += 256) {
        int n = l >> 5, c2 = l & 31;
        float v0 = 0.f, v1 = 0.f;
        if (n < KK) { v0 = wspan[n*CH + 2*c2]; v1 = wspan[n*CH + 2*c2 + 1]; }
        uint32_t hp = pack_bf2(v0, v1);
        uint32_t lp = pack_bf2(v0 - bf2_lo(hp), v1 - bf2_hi(hp));
        whi[n*SPAD + c2] = hp;
        wlo[n*SPAD + c2] = lp;
    }
    __syncthreads();

    const float* y0b = g_y0 + (size_t)b*CH*HWS + pix0;
    #pragma unroll
    for (int l = t; l < 32*32; l += 256) {
        int c2 = l >> 5, p4 = l & 31;
        float4 va = *(const float4*)(y0b + (size_t)(2*c2)*HWS + p4*4);
        float4 vb = *(const float4*)(y0b + (size_t)(2*c2+1)*HWS + p4*4);
        float a0[4] = {va.x, va.y, va.z, va.w};
        float b0v[4] = {vb.x, vb.y, vb.z, vb.w};
        const float s0 = bn[2*c2], h0 = bn[CH + 2*c2];
        const float s1 = bn[2*c2+1], h1 = bn[CH + 2*c2+1];
        #pragma unroll
        for (int j = 0; j < 4; j++) {
            float v0 = fmaxf(fmaf(a0[j], s0, h0), 0.f);
            float v1 = fmaxf(fmaf(b0v[j], s1, h1), 0.f);
            uint32_t hp = pack_bf2(v0, v1);
            uint32_t lp = pack_bf2(v0 - bf2_lo(hp), v1 - bf2_hi(hp));
            yhi[(p4*4 + j)*SPAD + c2] = hp;
            ylo[(p4*4 + j)*SPAD + c2] = lp;
        }
    }
    __syncthreads();

    const int gid = lid >> 2, tig = lid & 3;
    const int p0 = wid*16 + gid;
    float sacc[7][4];
    #pragma unroll
    for (int i = 0; i < 7; i++)
        #pragma unroll
        for (int j = 0; j < 4; j++) sacc[i][j] = 0.f;

    #pragma unroll
    for (int ks4 = 0; ks4 < 4; ks4++) {
        const int j0 = tig + ks4*8, j1 = j0 + 4;
        uint32_t ah0 = yhi[p0*SPAD + j0],     ah1 = yhi[(p0+8)*SPAD + j0];
        uint32_t ah2 = yhi[p0*SPAD + j1],     ah3 = yhi[(p0+8)*SPAD + j1];
        uint32_t al0 = ylo[p0*SPAD + j0],     al1 = ylo[(p0+8)*SPAD + j0];
        uint32_t al2 = ylo[p0*SPAD + j1],     al3 = ylo[(p0+8)*SPAD + j1];
        #pragma unroll
        for (int nt = 0; nt < 7; nt++) {
            const int n = nt*8 + gid;
            uint32_t bh0 = whi[n*SPAD + j0], bh1 = whi[n*SPAD + j1];
            uint32_t bl0 = wlo[n*SPAD + j0], bl1 = wlo[n*SPAD + j1];
            mma_bf16(sacc[nt], ah0, ah1, ah2, ah3, bh0, bh1);
            mma_bf16(sacc[nt], ah0, ah1, ah2, ah3, bl0, bl1);
            mma_bf16(sacc[nt], al0, al1, al2, al3, bh0, bh1);
        }
    }
    __syncthreads();

    float* pad = (float*)smw;           // [56 o][129]
    #pragma unroll
    for (int nt = 0; nt < 7; nt++) {
        const int o = nt*8 + 2*tig;
        pad[o*129 + p0]           = sacc[nt][0];
        pad[(o+1)*129 + p0]       = sacc[nt][1];
        pad[o*129 + p0 + 8]       = sacc[nt][2];
        pad[(o+1)*129 + p0 + 8]   = sacc[nt][3];
    }
    __syncthreads();

    float* kb = g_kern + (size_t)b*KK*HWS + pix0;
    #pragma unroll
    for (int l = t; l < KK*128; l += 256) {
        int o = l >> 7, p = l & 127;
        kb[(size_t)o*HWS + p] = pad[o*129 + p];
    }
}

// ================================================================ K3: involution + stats2 (exact R12 shape)
__global__ __launch_bounds__(256, 4) void k_invol(const float* __restrict__ x) {
    __shared__ __align__(16) float ks[KK*128];
    const int t = threadIdx.x;
    const int wg = t & 31;
    const int cl = t >> 5;
    const int b = blockIdx.y;
    const int z = blockIdx.z;
    const int pix0 = blockIdx.x * 128;
    const int ch0 = z*32 + cl*4;

    const float* kb = g_kern + (size_t)b*KK*HWS + pix0;
    #pragma unroll
    for (int l = t; l < KK*32; l += 256) {
        int p = l >> 5, q = l & 31;
        ((float4*)(ks + p*128))[q] = *(const float4*)(kb + (size_t)p*HWS + q*4);
    }
    __syncthreads();

    const int pp = pix0 + wg*4;
    const int h  = pp / WW;
    const int w0 = pp - h*WW;

    float acc[4][4];
    #pragma unroll
    for (int cc = 0; cc < 4; cc++)
        #pragma unroll
        for (int j = 0; j < 4; j++) acc[cc][j] = 0.f;

    const float* xbase = x + ((size_t)b*CH + ch0)*HWS;
    const float4 zero4 = make_float4(0.f, 0.f, 0.f, 0.f);
    #pragma unroll
    for (int kh = 0; kh < 7; kh++) {
        const int row = h + kh - 3;
        if (row < 0 || row >= HH) continue;
        float4 kv[7];
        #pragma unroll
        for (int kw = 0; kw < 7; kw++)
            kv[kw] = ((const float4*)(ks + (kh*7 + kw)*128))[wg];
        const float* xrow = xbase + (size_t)row*WW;
        #pragma unroll
        for (int cc = 0; cc < 4; cc++) {
            const float* xc = xrow + (size_t)cc*HWS;
            float4 v1 = *(const float4*)(xc + w0);
            float4 v0 = (w0 >= 4)   ? *(const float4*)(xc + w0 - 4) : zero4;
            float4 v2 = (w0 <= 104) ? *(const float4*)(xc + w0 + 4) : zero4;
            float xr[10] = {v0.y, v0.z, v0.w, v1.x, v1.y, v1.z, v1.w, v2.x, v2.y, v2.z};
            #pragma unroll
            for (int kw = 0; kw < 7; kw++) {
                acc[cc][0] = fmaf(xr[0 + kw], kv[kw].x, acc[cc][0]);
                acc[cc][1] = fmaf(xr[1 + kw], kv[kw].y, acc[cc][1]);
                acc[cc][2] = fmaf(xr[2 + kw], kv[kw].z, acc[cc][2]);
                acc[cc][3] = fmaf(xr[3 + kw], kv[kw].w, acc[cc][3]);
            }
        }
    }

    float* ob = g_out0 + ((size_t)b*CH + ch0)*HWS + pp;
    #pragma unroll
    for (int cc = 0; cc < 4; cc++) {
        float4 v; v.x = acc[cc][0]; v.y = acc[cc][1]; v.z = acc[cc][2]; v.w = acc[cc][3];
        *((float4*)(ob + (size_t)cc*HWS)) = v;
        float s = v.x + v.y + v.z + v.w;
        float q = v.x*v.x + v.y*v.y + v.z*v.z + v.w*v.w;
        #pragma unroll
        for (int off = 16; off; off >>= 1) {
            s += __shfl_down_sync(0xffffffffu, s, off);
            q += __shfl_down_sync(0xffffffffu, q, off);
        }
        if (wg == 0) {
            atomicAdd(&g_stats2[ch0 + cc], s);
            atomicAdd(&g_stats2[CH + ch0 + cc], q);
        }
    }
}

// ================================================================ K4: bn2 finalize + affine + PReLU
__global__ __launch_bounds__(256) void k_apply(const float* __restrict__ gamma,
                                               const float* __restrict__ beta,
                                               const float* __restrict__ alpha,
                                               float* __restrict__ out) {
    __shared__ float s_p[3];
    const int t = threadIdx.x;
    const int bc = blockIdx.x;
    const int chunk = blockIdx.y;
    const int c = bc & (CH-1);

    if (t == 0) {
        const float n = (float)NPIX;
        float mean = g_stats2[c] / n;
        float var  = g_stats2[CH + c] / n - mean*mean;
        float sc = gamma[c] * rsqrtf(var + 1e-3f);
        s_p[0] = sc;
        s_p[1] = beta[c] - mean*sc;
        s_p[2] = alpha[c];
    }
    if (bc == 0 && chunk == 0 && t < 2*CH) g_stats1[t] = 0.f;
    __syncthreads();

    const float sc = s_p[0], sh = s_p[1], al = s_p[2];
    const int base = chunk * (HWS/16);
    const float4* src = (const float4*)(g_out0 + (size_t)bc*HWS) + base;
    float4* dst = (float4*)(out + (size_t)bc*HWS) + base;
    #pragma unroll
    for (int i = t; i < HWS/16; i += 256) {
        float4 v = src[i];
        float u;
        u = fmaf(v.x, sc, sh); v.x = u > 0.f ? u : al*u;
        u = fmaf(v.y, sc, sh); v.y = u > 0.f ? u : al*u;
        u = fmaf(v.z, sc, sh); v.z = u > 0.f ? u : al*u;
        u = fmaf(v.w, sc, sh); v.w = u > 0.f ? u : al*u;
        dst[i] = v;
    }
}

// ----------------------------------------------------------------
extern "C" void kernel_launch(void* const* d_in, const int* in_sizes, int n_in,
                              void* d_out, int out_size) {
    const float* x     = (const float*)d_in[0];
    const float* wred  = (const float*)d_in[1];
    const float* g1    = (const float*)d_in[2];
    const float* b1    = (const float*)d_in[3];
    const float* wspan = (const float*)d_in[4];
    const float* g2    = (const float*)d_in[5];
    const float* b2    = (const float*)d_in[6];
    const float* alpha = (const float*)d_in[7];
    float* out = (float*)d_out;

    cudaFuncSetAttribute(k_reduce, cudaFuncAttributeMaxDynamicSharedMemorySize, RED_SMEM);
    cudaFuncSetAttribute(k_span,   cudaFuncAttributeMaxDynamicSharedMemorySize, SPAN_SMEM);

    k_reduce<<<dim3(HWS/128, BB), 256, RED_SMEM>>>(x, wred);
    k_span  <<<dim3(HWS/128, BB), 256, SPAN_SMEM>>>(wspan, g1, b1);
    k_invol <<<dim3(HWS/128, BB, 2), 256>>>(x);
    k_apply <<<dim3(BB*CH, 4), 256>>>(g2, b2, alpha, out);
}

// round 15
// speedup vs baseline: 1.0541x; 1.0106x over previous
#include <cuda_runtime.h>
#include <cuda_bf16.h>
#include <cstdint>

#define CH   64
#define HH   112
#define WW   112
#define HWS  12544
#define BB   4
#define KK   49
#define NPIX (BB*HWS)

// Scratch (device globals — no allocation allowed). Zero-initialized at load.
__device__ __align__(16) float g_y0  [BB*CH*HWS];   // reduce output (pre-BN1)
__device__ __align__(16) float g_kern[BB*KK*HWS];   // per-pixel kernels
__device__ __align__(16) float g_out0[BB*CH*HWS];   // involution output (pre-BN2)
__device__ float g_stats1[2*CH];
__device__ float g_stats2[2*CH];

// ---- packed bf16 helpers ----
__device__ __forceinline__ uint32_t pack_bf2(float lo, float hi) {
    __nv_bfloat162 p = __floats2bfloat162_rn(lo, hi);
    uint32_t u; *(__nv_bfloat162*)&u = p; return u;
}
__device__ __forceinline__ float bf2_lo(uint32_t u) { return __uint_as_float(u << 16); }
__device__ __forceinline__ float bf2_hi(uint32_t u) { return __uint_as_float(u & 0xFFFF0000u); }

__device__ __forceinline__ void mma_bf16(float c[4], uint32_t a0, uint32_t a1,
                                         uint32_t a2, uint32_t a3,
                                         uint32_t b0, uint32_t b1) {
    asm volatile(
        "mma.sync.aligned.m16n8k16.row.col.f32.bf16.bf16.f32 "
        "{%0,%1,%2,%3}, {%4,%5,%6,%7}, {%8,%9}, {%0,%1,%2,%3};"
        : "+f"(c[0]), "+f"(c[1]), "+f"(c[2]), "+f"(c[3])
        : "r"(a0), "r"(a1), "r"(a2), "r"(a3), "r"(b0), "r"(b1));
}

// ================================================================ K1: reduce GEMM (HMMA bf16x3) + stats1
#define APAD 37
#define BPAD 33
#define OFF_AHI 0
#define OFF_ALO (128*APAD)
#define OFF_BHI (2*128*APAD)
#define OFF_BLO (OFF_BHI + 64*BPAD)
#define RED_WORDS (OFF_BLO + 64*BPAD)
#define RED_SMEM (RED_WORDS*4)

__global__ __launch_bounds__(256, 4) void k_reduce(const float* __restrict__ x,
                                                   const float* __restrict__ wred) {
    extern __shared__ __align__(16) uint32_t smw[];
    uint32_t* ahix = smw + OFF_AHI;
    uint32_t* alox = smw + OFF_ALO;
    uint32_t* whix = smw + OFF_BHI;
    uint32_t* wlox = smw + OFF_BLO;

    const int t = threadIdx.x;
    const int wid = t >> 5, lid = t & 31;
    const int b = blockIdx.y;
    const int pix0 = blockIdx.x * 128;

    if (blockIdx.x == 0 && b == 0 && t < 2*CH) g_stats2[t] = 0.f;

    const float* xb = x + (size_t)b*CH*HWS + pix0;
    #pragma unroll
    for (int l = t; l < 32*32; l += 256) {
        int c2 = l >> 5, p4 = l & 31;
        float4 va = *(const float4*)(xb + (size_t)(2*c2)*HWS + p4*4);
        float4 vb = *(const float4*)(xb + (size_t)(2*c2+1)*HWS + p4*4);
        float a0[4] = {va.x, va.y, va.z, va.w};
        float b0[4] = {vb.x, vb.y, vb.z, vb.w};
        #pragma unroll
        for (int j = 0; j < 4; j++) {
            uint32_t hp = pack_bf2(a0[j], b0[j]);
            uint32_t lp = pack_bf2(a0[j] - bf2_lo(hp), b0[j] - bf2_hi(hp));
            ahix[(p4*4 + j)*APAD + c2] = hp;
            alox[(p4*4 + j)*APAD + c2] = lp;
        }
    }
    #pragma unroll
    for (int l = t; l < 32*64; l += 256) {
        int c2 = l & 31, n = l >> 5;
        float v0 = wred[n*CH + 2*c2];
        float v1 = wred[n*CH + 2*c2 + 1];
        uint32_t hp = pack_bf2(v0, v1);
        uint32_t lp = pack_bf2(v0 - bf2_lo(hp), v1 - bf2_hi(hp));
        whix[n*BPAD + c2] = hp;
        wlox[n*BPAD + c2] = lp;
    }
    __syncthreads();

    const int gid = lid >> 2, tig = lid & 3;
    const int p0 = wid*16 + gid;
    float acc[8][4];
    #pragma unroll
    for (int i = 0; i < 8; i++)
        #pragma unroll
        for (int j = 0; j < 4; j++) acc[i][j] = 0.f;

    #pragma unroll
    for (int ks = 0; ks < 4; ks++) {
        const int j0 = tig + ks*8, j1 = tig + 4 + ks*8;
        uint32_t ah0 = ahix[p0*APAD + j0],     ah1 = ahix[(p0+8)*APAD + j0];
        uint32_t ah2 = ahix[p0*APAD + j1],     ah3 = ahix[(p0+8)*APAD + j1];
        uint32_t al0 = alox[p0*APAD + j0],     al1 = alox[(p0+8)*APAD + j0];
        uint32_t al2 = alox[p0*APAD + j1],     al3 = alox[(p0+8)*APAD + j1];
        #pragma unroll
        for (int nt = 0; nt < 8; nt++) {
            const int n = nt*8 + gid;
            uint32_t bh0 = whix[n*BPAD + j0], bh1 = whix[n*BPAD + j1];
            uint32_t bl0 = wlox[n*BPAD + j0], bl1 = wlox[n*BPAD + j1];
            mma_bf16(acc[nt], ah0, ah1, ah2, ah3, bh0, bh1);
            mma_bf16(acc[nt], ah0, ah1, ah2, ah3, bl0, bl1);
            mma_bf16(acc[nt], al0, al1, al2, al3, bh0, bh1);
        }
    }
    __syncthreads();

    float* pad = (float*)smw;           // [64 o][129]
    #pragma unroll
    for (int nt = 0; nt < 8; nt++) {
        const int o = nt*8 + 2*tig;
        pad[o*129 + p0]           = acc[nt][0];
        pad[(o+1)*129 + p0]       = acc[nt][1];
        pad[o*129 + p0 + 8]       = acc[nt][2];
        pad[(o+1)*129 + p0 + 8]   = acc[nt][3];
    }
    __syncthreads();

    float* y0b = g_y0 + (size_t)b*CH*HWS + pix0;
    #pragma unroll
    for (int l = t; l < CH*128; l += 256) {
        int o = l >> 7, p = l & 127;
        y0b[(size_t)o*HWS + p] = pad[o*129 + p];
    }
    {
        const int o = t & 63, quarter = t >> 6;
        float s = 0.f, q = 0.f;
        #pragma unroll 8
        for (int i = 0; i < 32; i++) {
            float v = pad[o*129 + quarter*32 + i];
            s += v; q = fmaf(v, v, q);
        }
        atomicAdd(&g_stats1[o], s);
        atomicAdd(&g_stats1[CH + o], q);
    }
}

// ================================================================ K2: bn1 + span GEMM (HMMA bf16x3) -> g_kern
#define SPAD 33
#define S_YHI 0
#define S_YLO (128*SPAD)
#define S_WHI (2*128*SPAD)
#define S_WLO (S_WHI + 56*SPAD)
#define S_BN  (S_WLO + 56*SPAD)
#define SPAN_WORDS (S_BN + 128)
#define SPAN_SMEM (SPAN_WORDS*4)

__global__ __launch_bounds__(256, 4) void k_span(const float* __restrict__ wspan,
                                                 const float* __restrict__ g1,
                                                 const float* __restrict__ b1) {
    extern __shared__ __align__(16) uint32_t smw[];
    uint32_t* yhi = smw + S_YHI;
    uint32_t* ylo = smw + S_YLO;
    uint32_t* whi = smw + S_WHI;
    uint32_t* wlo = smw + S_WLO;
    float* bn = (float*)(smw + S_BN);

    const int t = threadIdx.x;
    const int wid = t >> 5, lid = t & 31;
    const int b = blockIdx.y;
    const int pix0 = blockIdx.x * 128;

    // ---- independent prologue: stage wspan (does NOT touch k_reduce output) ----
    #pragma unroll
    for (int l = t; l < 56*32; l += 256) {
        int n = l >> 5, c2 = l & 31;
        float v0 = 0.f, v1 = 0.f;
        if (n < KK) { v0 = wspan[n*CH + 2*c2]; v1 = wspan[n*CH + 2*c2 + 1]; }
        uint32_t hp = pack_bf2(v0, v1);
        uint32_t lp = pack_bf2(v0 - bf2_lo(hp), v1 - bf2_hi(hp));
        whi[n*SPAD + c2] = hp;
        wlo[n*SPAD + c2] = lp;
    }

    // ---- wait for k_reduce (PDL) before reading g_stats1 / g_y0 ----
    cudaGridDependencySynchronize();

    if (t < CH) {
        const float n = (float)NPIX;
        float mean = g_stats1[t] / n;
        float var  = g_stats1[CH + t] / n - mean*mean;
        float sc = g1[t] * rsqrtf(var + 1e-5f);
        bn[t]      = sc;
        bn[CH + t] = b1[t] - mean*sc;
    }
    __syncthreads();

    const float* y0b = g_y0 + (size_t)b*CH*HWS + pix0;
    #pragma unroll
    for (int l = t; l < 32*32; l += 256) {
        int c2 = l >> 5, p4 = l & 31;
        float4 va = *(const float4*)(y0b + (size_t)(2*c2)*HWS + p4*4);
        float4 vb = *(const float4*)(y0b + (size_t)(2*c2+1)*HWS + p4*4);
        float a0[4] = {va.x, va.y, va.z, va.w};
        float b0v[4] = {vb.x, vb.y, vb.z, vb.w};
        const float s0 = bn[2*c2], h0 = bn[CH + 2*c2];
        const float s1 = bn[2*c2+1], h1 = bn[CH + 2*c2+1];
        #pragma unroll
        for (int j = 0; j < 4; j++) {
            float v0 = fmaxf(fmaf(a0[j], s0, h0), 0.f);
            float v1 = fmaxf(fmaf(b0v[j], s1, h1), 0.f);
            uint32_t hp = pack_bf2(v0, v1);
            uint32_t lp = pack_bf2(v0 - bf2_lo(hp), v1 - bf2_hi(hp));
            yhi[(p4*4 + j)*SPAD + c2] = hp;
            ylo[(p4*4 + j)*SPAD + c2] = lp;
        }
    }
    __syncthreads();

    const int gid = lid >> 2, tig = lid & 3;
    const int p0 = wid*16 + gid;
    float sacc[7][4];
    #pragma unroll
    for (int i = 0; i < 7; i++)
        #pragma unroll
        for (int j = 0; j < 4; j++) sacc[i][j] = 0.f;

    #pragma unroll
    for (int ks4 = 0; ks4 < 4; ks4++) {
        const int j0 = tig + ks4*8, j1 = j0 + 4;
        uint32_t ah0 = yhi[p0*SPAD + j0],     ah1 = yhi[(p0+8)*SPAD + j0];
        uint32_t ah2 = yhi[p0*SPAD + j1],     ah3 = yhi[(p0+8)*SPAD + j1];
        uint32_t al0 = ylo[p0*SPAD + j0],     al1 = ylo[(p0+8)*SPAD + j0];
        uint32_t al2 = ylo[p0*SPAD + j1],     al3 = ylo[(p0+8)*SPAD + j1];
        #pragma unroll
        for (int nt = 0; nt < 7; nt++) {
            const int n = nt*8 + gid;
            uint32_t bh0 = whi[n*SPAD + j0], bh1 = whi[n*SPAD + j1];
            uint32_t bl0 = wlo[n*SPAD + j0], bl1 = wlo[n*SPAD + j1];
            mma_bf16(sacc[nt], ah0, ah1, ah2, ah3, bh0, bh1);
            mma_bf16(sacc[nt], ah0, ah1, ah2, ah3, bl0, bl1);
            mma_bf16(sacc[nt], al0, al1, al2, al3, bh0, bh1);
        }
    }
    __syncthreads();

    float* pad = (float*)smw;           // [56 o][129]
    #pragma unroll
    for (int nt = 0; nt < 7; nt++) {
        const int o = nt*8 + 2*tig;
        pad[o*129 + p0]           = sacc[nt][0];
        pad[(o+1)*129 + p0]       = sacc[nt][1];
        pad[o*129 + p0 + 8]       = sacc[nt][2];
        pad[(o+1)*129 + p0 + 8]   = sacc[nt][3];
    }
    __syncthreads();

    float* kb = g_kern + (size_t)b*KK*HWS + pix0;
    #pragma unroll
    for (int l = t; l < KK*128; l += 256) {
        int o = l >> 7, p = l & 127;
        kb[(size_t)o*HWS + p] = pad[o*129 + p];
    }
}

// ================================================================ K3: involution + stats2
__global__ __launch_bounds__(256, 4) void k_invol(const float* __restrict__ x) {
    __shared__ __align__(16) float ks[KK*128];
    const int t = threadIdx.x;
    const int wg = t & 31;
    const int cl = t >> 5;
    const int b = blockIdx.y;
    const int z = blockIdx.z;
    const int pix0 = blockIdx.x * 128;
    const int ch0 = z*32 + cl*4;

    cudaGridDependencySynchronize();    // wait for k_span (PDL)

    const float* kb = g_kern + (size_t)b*KK*HWS + pix0;
    #pragma unroll
    for (int l = t; l < KK*32; l += 256) {
        int p = l >> 5, q = l & 31;
        ((float4*)(ks + p*128))[q] = *(const float4*)(kb + (size_t)p*HWS + q*4);
    }
    __syncthreads();

    const int pp = pix0 + wg*4;
    const int h  = pp / WW;
    const int w0 = pp - h*WW;

    float acc[4][4];
    #pragma unroll
    for (int cc = 0; cc < 4; cc++)
        #pragma unroll
        for (int j = 0; j < 4; j++) acc[cc][j] = 0.f;

    const float* xbase = x + ((size_t)b*CH + ch0)*HWS;
    const float4 zero4 = make_float4(0.f, 0.f, 0.f, 0.f);
    #pragma unroll
    for (int kh = 0; kh < 7; kh++) {
        const int row = h + kh - 3;
        if (row < 0 || row >= HH) continue;
        float4 kv[7];
        #pragma unroll
        for (int kw = 0; kw < 7; kw++)
            kv[kw] = ((const float4*)(ks + (kh*7 + kw)*128))[wg];
        const float* xrow = xbase + (size_t)row*WW;
        #pragma unroll
        for (int cc = 0; cc < 4; cc++) {
            const float* xc = xrow + (size_t)cc*HWS;
            float4 v1 = *(const float4*)(xc + w0);
            float4 v0 = (w0 >= 4)   ? *(const float4*)(xc + w0 - 4) : zero4;
            float4 v2 = (w0 <= 104) ? *(const float4*)(xc + w0 + 4) : zero4;
            float xr[10] = {v0.y, v0.z, v0.w, v1.x, v1.y, v1.z, v1.w, v2.x, v2.y, v2.z};
            #pragma unroll
            for (int kw = 0; kw < 7; kw++) {
                acc[cc][0] = fmaf(xr[0 + kw], kv[kw].x, acc[cc][0]);
                acc[cc][1] = fmaf(xr[1 + kw], kv[kw].y, acc[cc][1]);
                acc[cc][2] = fmaf(xr[2 + kw], kv[kw].z, acc[cc][2]);
                acc[cc][3] = fmaf(xr[3 + kw], kv[kw].w, acc[cc][3]);
            }
        }
    }

    float* ob = g_out0 + ((size_t)b*CH + ch0)*HWS + pp;
    #pragma unroll
    for (int cc = 0; cc < 4; cc++) {
        float4 v; v.x = acc[cc][0]; v.y = acc[cc][1]; v.z = acc[cc][2]; v.w = acc[cc][3];
        *((float4*)(ob + (size_t)cc*HWS)) = v;
        float s = v.x + v.y + v.z + v.w;
        float q = v.x*v.x + v.y*v.y + v.z*v.z + v.w*v.w;
        #pragma unroll
        for (int off = 16; off; off >>= 1) {
            s += __shfl_down_sync(0xffffffffu, s, off);
            q += __shfl_down_sync(0xffffffffu, q, off);
        }
        if (wg == 0) {
            atomicAdd(&g_stats2[ch0 + cc], s);
            atomicAdd(&g_stats2[CH + ch0 + cc], q);
        }
    }
}

// ================================================================ K4: bn2 finalize + affine + PReLU
__global__ __launch_bounds__(256) void k_apply(const float* __restrict__ gamma,
                                               const float* __restrict__ beta,
                                               const float* __restrict__ alpha,
                                               float* __restrict__ out) {
    __shared__ float s_p[3];
    const int t = threadIdx.x;
    const int bc = blockIdx.x;
    const int chunk = blockIdx.y;
    const int c = bc & (CH-1);

    cudaGridDependencySynchronize();    // wait for k_invol (PDL)

    if (t == 0) {
        const float n = (float)NPIX;
        float mean = g_stats2[c] / n;
        float var  = g_stats2[CH + c] / n - mean*mean;
        float sc = gamma[c] * rsqrtf(var + 1e-3f);
        s_p[0] = sc;
        s_p[1] = beta[c] - mean*sc;
        s_p[2] = alpha[c];
    }
    if (bc == 0 && chunk == 0 && t < 2*CH) g_stats1[t] = 0.f;
    __syncthreads();

    const float sc = s_p[0], sh = s_p[1], al = s_p[2];
    const int base = chunk * (HWS/16);
    const float4* src = (const float4*)(g_out0 + (size_t)bc*HWS) + base;
    float4* dst = (float4*)(out + (size_t)bc*HWS) + base;
    #pragma unroll
    for (int i = t; i < HWS/16; i += 256) {
        float4 v = src[i];
        float u;
        u = fmaf(v.x, sc, sh); v.x = u > 0.f ? u : al*u;
        u = fmaf(v.y, sc, sh); v.y = u > 0.f ? u : al*u;
        u = fmaf(v.z, sc, sh); v.z = u > 0.f ? u : al*u;
        u = fmaf(v.w, sc, sh); v.w = u > 0.f ? u : al*u;
        dst[i] = v;
    }
}

// ----------------------------------------------------------------
extern "C" void kernel_launch(void* const* d_in, const int* in_sizes, int n_in,
                              void* d_out, int out_size) {
    const float* x     = (const float*)d_in[0];
    const float* wred  = (const float*)d_in[1];
    const float* g1    = (const float*)d_in[2];
    const float* b1    = (const float*)d_in[3];
    const float* wspan = (const float*)d_in[4];
    const float* g2    = (const float*)d_in[5];
    const float* b2    = (const float*)d_in[6];
    const float* alpha = (const float*)d_in[7];
    float* out = (float*)d_out;

    cudaFuncSetAttribute(k_reduce, cudaFuncAttributeMaxDynamicSharedMemorySize, RED_SMEM);
    cudaFuncSetAttribute(k_span,   cudaFuncAttributeMaxDynamicSharedMemorySize, SPAN_SMEM);

    // K1: normal launch
    k_reduce<<<dim3(HWS/128, BB), 256, RED_SMEM>>>(x, wred);

    // K2..K4: PDL launches (overlap launch setup + independent prologue with predecessor)
    cudaLaunchAttribute pdl[1];
    pdl[0].id = cudaLaunchAttributeProgrammaticStreamSerialization;
    pdl[0].val.programmaticStreamSerializationAllowed = 1;

    {
        cudaLaunchConfig_t cfg = {};
        cfg.gridDim = dim3(HWS/128, BB);
        cfg.blockDim = dim3(256);
        cfg.dynamicSmemBytes = SPAN_SMEM;
        cfg.stream = 0;
        cfg.attrs = pdl;
        cfg.numAttrs = 1;
        cudaLaunchKernelEx(&cfg, k_span, wspan, g1, b1);
    }
    {
        cudaLaunchConfig_t cfg = {};
        cfg.gridDim = dim3(HWS/128, BB, 2);
        cfg.blockDim = dim3(256);
        cfg.dynamicSmemBytes = 0;
        cfg.stream = 0;
        cfg.attrs = pdl;
        cfg.numAttrs = 1;
        cudaLaunchKernelEx(&cfg, k_invol, x);
    }
    {
        cudaLaunchConfig_t cfg = {};
        cfg.gridDim = dim3(BB*CH, 4);
        cfg.blockDim = dim3(256);
        cfg.dynamicSmemBytes = 0;
        cfg.stream = 0;
        cfg.attrs = pdl;
        cfg.numAttrs = 1;
        cudaLaunchKernelEx(&cfg, k_apply, g2, b2, alpha, out);
    }
}